// round 2
// baseline (speedup 1.0000x reference)
#include <cuda_runtime.h>
#include <math.h>

// Problem constants
#define Sn 8192
#define Dn 2048
#define En 64
#define Cn 128
#define MAXN 1024   // max tokens gathered per expert (mean 128, sigma ~11)

static const long long SECn = (long long)Sn * En * Cn;  // 67,108,864

// ---------------- device scratch (no allocations allowed) ----------------
__device__ float g_part[2 * Sn * En];   // split-K partial logits, 4MB
__device__ float g_gate[Sn];            // gate value at argmax expert
__device__ int   g_expert[Sn];          // argmax expert per token
__device__ int   g_code[Sn];            // -1 dropped, else expert | (slot<<6)
__device__ float g_colsum[En];          // column sums of gates (for me)
__device__ int   g_cnt[En];             // raw expert counts (mask1 sums)

// ---------------- init ----------------
__global__ void init_kernel() {
    int t = threadIdx.x;
    if (t < En) { g_colsum[t] = 0.f; g_cnt[t] = 0; }
}

// ---------------- GEMM: logits = x @ wg^T, split-K=2 ----------------
// grid (128, 2), block 256. Tile: 64 tokens x 64 experts, K-chunk 32.
__global__ __launch_bounds__(256) void gemm_kernel(const float* __restrict__ x,
                                                   const float* __restrict__ wg) {
    const int m0 = blockIdx.x * 64;
    const int k0 = blockIdx.y * 1024;
    __shared__ float xsT[32][68];
    __shared__ float wsT[32][68];

    const int tid = threadIdx.x;
    const int tx = tid & 15;   // expert group
    const int ty = tid >> 4;   // token group

    float acc[4][4];
#pragma unroll
    for (int i = 0; i < 4; i++)
#pragma unroll
        for (int j = 0; j < 4; j++) acc[i][j] = 0.f;

    for (int kb = 0; kb < 1024; kb += 32) {
#pragma unroll
        for (int i = 0; i < 2; i++) {
            int v = tid + i * 256;       // 0..511
            int row = v >> 3;            // 0..63
            int kq = v & 7;              // 0..7 (float4 along K)
            const float4 xv = *(const float4*)(x + (size_t)(m0 + row) * Dn + (k0 + kb + (kq << 2)));
            xsT[(kq << 2) + 0][row] = xv.x;
            xsT[(kq << 2) + 1][row] = xv.y;
            xsT[(kq << 2) + 2][row] = xv.z;
            xsT[(kq << 2) + 3][row] = xv.w;
            const float4 wv = *(const float4*)(wg + (size_t)row * Dn + (k0 + kb + (kq << 2)));
            wsT[(kq << 2) + 0][row] = wv.x;
            wsT[(kq << 2) + 1][row] = wv.y;
            wsT[(kq << 2) + 2][row] = wv.z;
            wsT[(kq << 2) + 3][row] = wv.w;
        }
        __syncthreads();
#pragma unroll
        for (int kk = 0; kk < 32; kk++) {
            float4 a = *(const float4*)&xsT[kk][ty << 2];
            float4 b = *(const float4*)&wsT[kk][tx << 2];
            float av[4] = {a.x, a.y, a.z, a.w};
            float bv[4] = {b.x, b.y, b.z, b.w};
#pragma unroll
            for (int i = 0; i < 4; i++)
#pragma unroll
                for (int j = 0; j < 4; j++)
                    acc[i][j] = fmaf(av[i], bv[j], acc[i][j]);
        }
        __syncthreads();
    }

    float* op = g_part + (size_t)blockIdx.y * (Sn * En);
#pragma unroll
    for (int i = 0; i < 4; i++) {
        float4 vv = make_float4(acc[i][0], acc[i][1], acc[i][2], acc[i][3]);
        *(float4*)(op + (size_t)(m0 + (ty << 2) + i) * En + (tx << 2)) = vv;
    }
}

// ---------------- softmax + argmax + column sums + counts ----------------
// one warp per token, 8 tokens per block, 1024 blocks
__global__ __launch_bounds__(256) void softmax_kernel() {
    __shared__ float scs[En];
    const int warp = threadIdx.x >> 5;
    const int lane = threadIdx.x & 31;
    const int s = blockIdx.x * 8 + warp;

    if (threadIdx.x < En) scs[threadIdx.x] = 0.f;
    __syncthreads();

    const float* p0 = g_part + (size_t)s * En;
    const float* p1 = g_part + (size_t)(Sn * En) + (size_t)s * En;
    float v0 = p0[lane] + p1[lane];
    float v1 = p0[lane + 32] + p1[lane + 32];

    // row max
    float m = fmaxf(v0, v1);
#pragma unroll
    for (int o = 16; o; o >>= 1) m = fmaxf(m, __shfl_xor_sync(0xffffffffu, m, o));

    float e0 = expf(v0 - m), e1 = expf(v1 - m);
    float ss = e0 + e1;
#pragma unroll
    for (int o = 16; o; o >>= 1) ss += __shfl_xor_sync(0xffffffffu, ss, o);
    float inv = 1.0f / ss;
    float gg0 = e0 * inv, gg1 = e1 * inv;

    // argmax with tie-break: smallest index (matches jnp.argmax)
    float bv; int bi;
    if (v0 >= v1) { bv = v0; bi = lane; } else { bv = v1; bi = lane + 32; }
#pragma unroll
    for (int o = 16; o; o >>= 1) {
        float ov = __shfl_xor_sync(0xffffffffu, bv, o);
        int oi = __shfl_xor_sync(0xffffffffu, bi, o);
        if (ov > bv || (ov == bv && oi < bi)) { bv = ov; bi = oi; }
    }
    // gate value at argmax (bi is warp-uniform now)
    float gsel = __shfl_sync(0xffffffffu, (bi < 32) ? gg0 : gg1, bi & 31);

    // block-level column sums, then one global atomic per expert per block
    atomicAdd(&scs[lane], gg0);
    atomicAdd(&scs[lane + 32], gg1);

    if (lane == 0) {
        g_gate[s] = gsel;
        g_expert[s] = bi;
        g_code[s] = -1;
        atomicAdd(&g_cnt[bi], 1);
    }
    __syncthreads();
    if (threadIdx.x < En) atomicAdd(&g_colsum[threadIdx.x], scs[threadIdx.x]);
}

// ---------------- exact JAX threefry2x32 noise (PARTITIONABLE path) ----------------
// Modern JAX default (jax_threefry_partitionable=True):
//   per-element 64-bit linear counter j -> x0 = hi32(j) = 0, x1 = lo32(j) = j
//   threefry2x32 with key (0, 42); 32-bit output = out0 ^ out1
//   uniform = bitcast((bits >> 9) | 0x3F800000) - 1
__device__ __forceinline__ unsigned rotl32(unsigned v, int d) {
    return (v << d) | (v >> (32 - d));
}
__device__ __forceinline__ float jax_noise(int s, int e) {
    unsigned j = (unsigned)(s * En + e);
    unsigned x0 = 0u;
    unsigned x1 = j;

    const unsigned ks0 = 0u;
    const unsigned ks1 = 42u;
    const unsigned ks2 = 0u ^ 42u ^ 0x1BD11BDAu;

    x0 += ks0; x1 += ks1;
#define TF_ROUND(R) { x0 += x1; x1 = rotl32(x1, R); x1 ^= x0; }
    TF_ROUND(13) TF_ROUND(15) TF_ROUND(26) TF_ROUND(6)
    x0 += ks1; x1 += ks2 + 1u;
    TF_ROUND(17) TF_ROUND(29) TF_ROUND(16) TF_ROUND(24)
    x0 += ks2; x1 += ks0 + 2u;
    TF_ROUND(13) TF_ROUND(15) TF_ROUND(26) TF_ROUND(6)
    x0 += ks0; x1 += ks1 + 3u;
    TF_ROUND(17) TF_ROUND(29) TF_ROUND(16) TF_ROUND(24)
    x0 += ks1; x1 += ks2 + 4u;
    TF_ROUND(13) TF_ROUND(15) TF_ROUND(26) TF_ROUND(6)
    x0 += ks2; x1 += ks0 + 5u;
#undef TF_ROUND
    unsigned bits = x0 ^ x1;
    return __uint_as_float((bits >> 9) | 0x3F800000u) - 1.0f;
}

// ---------------- per-expert capacity selection + slot assignment ----------------
// one block per expert
__global__ __launch_bounds__(256) void capacity_kernel() {
    const int e = blockIdx.x;
    __shared__ int   sidx[MAXN];
    __shared__ float snoi[MAXN];
    __shared__ char  skeep[MAXN];
    __shared__ int   scnt;

    if (threadIdx.x == 0) scnt = 0;
    __syncthreads();

    for (int s = threadIdx.x; s < Sn; s += blockDim.x) {
        if (g_expert[s] == e) {
            int p = atomicAdd(&scnt, 1);
            if (p < MAXN) { sidx[p] = s; snoi[p] = jax_noise(s, e); }
        }
    }
    __syncthreads();
    int n = scnt < MAXN ? scnt : MAXN;

    // keep = rank < capacity by (noise desc, index asc); lax.top_k is index-stable
    for (int i = threadIdx.x; i < n; i += blockDim.x) {
        char k = 1;
        if (n > Cn) {
            int r = 0;
            float ni = snoi[i];
            int ii = sidx[i];
            for (int jj = 0; jj < n; jj++) {
                float nj = snoi[jj];
                r += (nj > ni) || (nj == ni && sidx[jj] < ii);
            }
            k = (r < Cn) ? 1 : 0;
        }
        skeep[i] = k;
    }
    __syncthreads();

    // slot = rank by token index among kept (cumsum semantics)
    for (int i = threadIdx.x; i < n; i += blockDim.x) {
        if (!skeep[i]) continue;
        int ii = sidx[i];
        int slot = 0;
        for (int jj = 0; jj < n; jj++) slot += (skeep[jj] && sidx[jj] < ii);
        g_code[ii] = e | (slot << 6);
    }
}

// ---------------- l_aux + exp_counts ----------------
__global__ void finalize_kernel(float* __restrict__ out, long long out_size) {
    __shared__ float sv[En];
    int t = threadIdx.x;  // 64 threads
    sv[t] = g_colsum[t] * (float)g_cnt[t];
    __syncthreads();
    if (t == 0) {
        float sum = 0.f;
        for (int i = 0; i < En; i++) sum += sv[i];
        // l_aux = sum_e (colsum/S)*(cnt/S) * E
        float laux = sum * ((float)En / ((float)Sn * (float)Sn));
        if (out_size > 0) out[0] = laux;
    }
    long long idx = 1 + 2 * SECn + t;
    if (idx < out_size) out[idx] = (float)g_cnt[t];
}

// ---------------- bulk output writer (combine + dispatch), one warp per row ----------------
__global__ __launch_bounds__(256) void writer_kernel(float* __restrict__ out, long long out_size) {
    const long long NR = (long long)Sn * En;  // 524288 rows per region
    long long row = (long long)blockIdx.x * 8 + (threadIdx.x >> 5);
    const int lane = threadIdx.x & 31;
    const int region = row >= NR;
    long long r = region ? row - NR : row;
    const int s = (int)(r >> 6);
    const int e = (int)(r & 63);

    int code = g_code[s];
    int slot = -1;
    float val = 0.f;
    if (code >= 0 && (code & 63) == e) {
        slot = code >> 6;
        val = region ? 1.0f : g_gate[s];
    }

    long long base = 1 + (region ? SECn : 0) + r * (long long)Cn;
    int c0 = lane << 2;
    float v0 = (slot == c0 + 0) ? val : 0.f;
    float v1 = (slot == c0 + 1) ? val : 0.f;
    float v2 = (slot == c0 + 2) ? val : 0.f;
    float v3 = (slot == c0 + 3) ? val : 0.f;
    long long p = base + c0;
    if (p + 3 < out_size) {
        out[p + 0] = v0;
        out[p + 1] = v1;
        out[p + 2] = v2;
        out[p + 3] = v3;
    }
}

// ---------------- launch ----------------
extern "C" void kernel_launch(void* const* d_in, const int* in_sizes, int n_in,
                              void* d_out, int out_size) {
    const float* x  = (const float*)d_in[0];   // [S, D] f32
    const float* wg = (const float*)d_in[1];   // [E, D] f32
    float* out = (float*)d_out;
    long long osz = (long long)out_size;

    init_kernel<<<1, 128>>>();
    gemm_kernel<<<dim3(128, 2), 256>>>(x, wg);
    softmax_kernel<<<1024, 256>>>();
    capacity_kernel<<<En, 256>>>();
    finalize_kernel<<<1, 64>>>(out, osz);
    writer_kernel<<<131072, 256>>>(out, osz);
}

// round 3
// speedup vs baseline: 1.4711x; 1.4711x over previous
#include <cuda_runtime.h>
#include <math.h>

// Problem constants
#define Sn 8192
#define Dn 2048
#define En 64
#define Cn 128
#define MAXN 1024   // max tokens gathered per expert (mean 128, sigma ~11)

static const long long SECn = (long long)Sn * En * Cn;  // 67,108,864

// ---------------- device scratch (no allocations allowed) ----------------
__device__ float g_part[2 * Sn * En];   // split-K partial logits, 4MB
__device__ float g_gate[Sn];            // gate value at argmax expert
__device__ int   g_list[En * MAXN];     // per-expert gathered token indices
__device__ float g_colsum[En];          // column sums of gates (for me)
__device__ int   g_cnt[En];             // raw expert counts (mask1 sums)

// ---------------- init ----------------
__global__ void init_kernel() {
    int t = threadIdx.x;
    if (t < En) { g_colsum[t] = 0.f; g_cnt[t] = 0; }
}

// ---------------- fused GEMM + zero-fill ----------------
// logits = x @ wg^T, split-K=2. grid (128, 2), block 256.
// Tile: 64 tokens x 64 experts, K-chunk 32. Accumulation order identical to R2
// (bit-faithful argmax). Additionally each block zero-fills a 2MB slice of the
// output buffer, interleaved with the k-loop so stores overlap FFMA work.
// 256 blocks x 524288 floats = 134,217,728 floats = [0, 1+2*SEC-1) coverage.
__global__ __launch_bounds__(256) void gemm_fill_kernel(const float* __restrict__ x,
                                                        const float* __restrict__ wg,
                                                        float* __restrict__ out) {
    const int m0 = blockIdx.x * 64;
    const int k0 = blockIdx.y * 1024;
    __shared__ float xsT[32][68];
    __shared__ float wsT[32][68];

    const int tid = threadIdx.x;
    const int tx = tid & 15;   // expert group
    const int ty = tid >> 4;   // token group

    const size_t fb = ((size_t)blockIdx.y * 128 + blockIdx.x) * 524288 + (size_t)(tid << 2);
    const float4 z4 = make_float4(0.f, 0.f, 0.f, 0.f);

    float acc[4][4];
#pragma unroll
    for (int i = 0; i < 4; i++)
#pragma unroll
        for (int j = 0; j < 4; j++) acc[i][j] = 0.f;

    for (int kb = 0; kb < 1024; kb += 32) {
#pragma unroll
        for (int i = 0; i < 2; i++) {
            int v = tid + i * 256;       // 0..511
            int row = v >> 3;            // 0..63
            int kq = v & 7;              // 0..7 (float4 along K)
            const float4 xv = *(const float4*)(x + (size_t)(m0 + row) * Dn + (k0 + kb + (kq << 2)));
            xsT[(kq << 2) + 0][row] = xv.x;
            xsT[(kq << 2) + 1][row] = xv.y;
            xsT[(kq << 2) + 2][row] = xv.z;
            xsT[(kq << 2) + 3][row] = xv.w;
            const float4 wv = *(const float4*)(wg + (size_t)row * Dn + (k0 + kb + (kq << 2)));
            wsT[(kq << 2) + 0][row] = wv.x;
            wsT[(kq << 2) + 1][row] = wv.y;
            wsT[(kq << 2) + 2][row] = wv.z;
            wsT[(kq << 2) + 3][row] = wv.w;
        }
        __syncthreads();

        // interleaved zero-fill: 16 float4 (256B/thread) per k-chunk
        {
            size_t base = fb + (size_t)(kb >> 5) * 16384;  // iter * 16 slots * 1024 floats
#pragma unroll
            for (int q = 0; q < 16; q++)
                *(float4*)(out + base + (size_t)q * 1024) = z4;
        }

#pragma unroll
        for (int kk = 0; kk < 32; kk++) {
            float4 a = *(const float4*)&xsT[kk][ty << 2];
            float4 b = *(const float4*)&wsT[kk][tx << 2];
            float av[4] = {a.x, a.y, a.z, a.w};
            float bv[4] = {b.x, b.y, b.z, b.w};
#pragma unroll
            for (int i = 0; i < 4; i++)
#pragma unroll
                for (int j = 0; j < 4; j++)
                    acc[i][j] = fmaf(av[i], bv[j], acc[i][j]);
        }
        __syncthreads();
    }

    float* op = g_part + (size_t)blockIdx.y * (Sn * En);
#pragma unroll
    for (int i = 0; i < 4; i++) {
        float4 vv = make_float4(acc[i][0], acc[i][1], acc[i][2], acc[i][3]);
        *(float4*)(op + (size_t)(m0 + (ty << 2) + i) * En + (tx << 2)) = vv;
    }
}

// ---------------- softmax + argmax + column sums + counts + expert lists ----------------
// one warp per token, 8 tokens per block, 1024 blocks
__global__ __launch_bounds__(256) void softmax_kernel() {
    __shared__ float scs[En];
    const int warp = threadIdx.x >> 5;
    const int lane = threadIdx.x & 31;
    const int s = blockIdx.x * 8 + warp;

    if (threadIdx.x < En) scs[threadIdx.x] = 0.f;
    __syncthreads();

    const float* p0 = g_part + (size_t)s * En;
    const float* p1 = g_part + (size_t)(Sn * En) + (size_t)s * En;
    float v0 = p0[lane] + p1[lane];
    float v1 = p0[lane + 32] + p1[lane + 32];

    // row max
    float m = fmaxf(v0, v1);
#pragma unroll
    for (int o = 16; o; o >>= 1) m = fmaxf(m, __shfl_xor_sync(0xffffffffu, m, o));

    float e0 = expf(v0 - m), e1 = expf(v1 - m);
    float ss = e0 + e1;
#pragma unroll
    for (int o = 16; o; o >>= 1) ss += __shfl_xor_sync(0xffffffffu, ss, o);
    float inv = 1.0f / ss;
    float gg0 = e0 * inv, gg1 = e1 * inv;

    // argmax with tie-break: smallest index (matches jnp.argmax)
    float bv; int bi;
    if (v0 >= v1) { bv = v0; bi = lane; } else { bv = v1; bi = lane + 32; }
#pragma unroll
    for (int o = 16; o; o >>= 1) {
        float ov = __shfl_xor_sync(0xffffffffu, bv, o);
        int oi = __shfl_xor_sync(0xffffffffu, bi, o);
        if (ov > bv || (ov == bv && oi < bi)) { bv = ov; bi = oi; }
    }
    // gate value at argmax (bi is warp-uniform now)
    float gsel = __shfl_sync(0xffffffffu, (bi < 32) ? gg0 : gg1, bi & 31);

    // block-level column sums, then one global atomic per expert per block
    atomicAdd(&scs[lane], gg0);
    atomicAdd(&scs[lane + 32], gg1);

    if (lane == 0) {
        g_gate[s] = gsel;
        int p = atomicAdd(&g_cnt[bi], 1);
        if (p < MAXN) g_list[bi * MAXN + p] = s;
    }
    __syncthreads();
    if (threadIdx.x < En) atomicAdd(&g_colsum[threadIdx.x], scs[threadIdx.x]);
}

// ---------------- exact JAX threefry2x32 noise (partitionable path) ----------------
__device__ __forceinline__ unsigned rotl32(unsigned v, int d) {
    return (v << d) | (v >> (32 - d));
}
__device__ __forceinline__ float jax_noise(int s, int e) {
    unsigned x0 = 0u;
    unsigned x1 = (unsigned)(s * En + e);

    const unsigned ks0 = 0u;
    const unsigned ks1 = 42u;
    const unsigned ks2 = 0u ^ 42u ^ 0x1BD11BDAu;

    x0 += ks0; x1 += ks1;
#define TF_ROUND(R) { x0 += x1; x1 = rotl32(x1, R); x1 ^= x0; }
    TF_ROUND(13) TF_ROUND(15) TF_ROUND(26) TF_ROUND(6)
    x0 += ks1; x1 += ks2 + 1u;
    TF_ROUND(17) TF_ROUND(29) TF_ROUND(16) TF_ROUND(24)
    x0 += ks2; x1 += ks0 + 2u;
    TF_ROUND(13) TF_ROUND(15) TF_ROUND(26) TF_ROUND(6)
    x0 += ks0; x1 += ks1 + 3u;
    TF_ROUND(17) TF_ROUND(29) TF_ROUND(16) TF_ROUND(24)
    x0 += ks1; x1 += ks2 + 4u;
    TF_ROUND(13) TF_ROUND(15) TF_ROUND(26) TF_ROUND(6)
    x0 += ks2; x1 += ks0 + 5u;
#undef TF_ROUND
    unsigned bits = x0 ^ x1;
    return __uint_as_float((bits >> 9) | 0x3F800000u) - 1.0f;
}

// ---------------- l_aux + exp_counts + tail element ----------------
// Runs BEFORE capacity_kernel: zeroes the single dispatch element not covered
// by the bulk fill (index 1+2*SEC-1); capacity may overwrite it with 1.0f.
__global__ void finalize_kernel(float* __restrict__ out, long long out_size) {
    __shared__ float sv[En];
    int t = threadIdx.x;  // 64 threads
    sv[t] = g_colsum[t] * (float)g_cnt[t];
    __syncthreads();
    if (t == 0) {
        float sum = 0.f;
        for (int i = 0; i < En; i++) sum += sv[i];
        float laux = sum * ((float)En / ((float)Sn * (float)Sn));
        if (out_size > 0) out[0] = laux;
        long long tail = 2 * SECn;  // last dispatch element (not float4-covered)
        if (tail < out_size) out[tail] = 0.f;
    }
    long long idx = 1 + 2 * SECn + t;
    if (idx < out_size) out[idx] = (float)g_cnt[t];
}

// ---------------- per-expert capacity selection + direct scatter ----------------
// one block per expert; reads prebuilt list, ranks by (noise desc, index asc),
// assigns slots by token-index rank among kept, writes nonzeros directly.
__global__ __launch_bounds__(256) void capacity_kernel(float* __restrict__ out,
                                                       long long out_size) {
    const int e = blockIdx.x;
    __shared__ int   sidx[MAXN];
    __shared__ float snoi[MAXN];
    __shared__ char  skeep[MAXN];

    int n = g_cnt[e];
    if (n > MAXN) n = MAXN;

    for (int i = threadIdx.x; i < n; i += blockDim.x) {
        int s = g_list[e * MAXN + i];
        sidx[i] = s;
        snoi[i] = jax_noise(s, e);
    }
    __syncthreads();

    // keep = rank < capacity by (noise desc, index asc); lax.top_k is index-stable
    for (int i = threadIdx.x; i < n; i += blockDim.x) {
        char k = 1;
        if (n > Cn) {
            int r = 0;
            float ni = snoi[i];
            int ii = sidx[i];
            for (int jj = 0; jj < n; jj++) {
                float nj = snoi[jj];
                r += (nj > ni) || (nj == ni && sidx[jj] < ii);
            }
            k = (r < Cn) ? 1 : 0;
        }
        skeep[i] = k;
    }
    __syncthreads();

    // slot = rank by token index among kept (cumsum semantics); scatter outputs
    for (int i = threadIdx.x; i < n; i += blockDim.x) {
        if (!skeep[i]) continue;
        int ii = sidx[i];
        int slot = 0;
        for (int jj = 0; jj < n; jj++) slot += (skeep[jj] && sidx[jj] < ii);
        long long r = (long long)ii * En + e;
        long long p = 1 + r * (long long)Cn + slot;
        if (p < out_size) out[p] = g_gate[ii];
        if (p + SECn < out_size) out[p + SECn] = 1.0f;
    }
}

// ---------------- launch ----------------
extern "C" void kernel_launch(void* const* d_in, const int* in_sizes, int n_in,
                              void* d_out, int out_size) {
    const float* x  = (const float*)d_in[0];   // [S, D] f32
    const float* wg = (const float*)d_in[1];   // [E, D] f32
    float* out = (float*)d_out;
    long long osz = (long long)out_size;

    init_kernel<<<1, 128>>>();
    gemm_fill_kernel<<<dim3(128, 2), 256>>>(x, wg, out);
    softmax_kernel<<<1024, 256>>>();
    finalize_kernel<<<1, 64>>>(out, osz);
    capacity_kernel<<<En, 256>>>(out, osz);
}